// round 7
// baseline (speedup 1.0000x reference)
#include <cuda_runtime.h>
#include <cstdint>

// ============================================================================
// WignerKernelReducedCost — GB300 sm_103a
//
// Math reduction (see R0): outputs per batch element b are
//   r1 = x0[0,0]
//   r2 = X2[0,+1][0,0]
//   r3 = sum_{L,s=+1} 1/(2L+1) sum_{mu,mp} (-1)^{mu+mp} X2[L,+][mu,mp] x_L[-mu,-mp]
//   r4 = sum_{L,s}    1/(2L+1) sum_{mu,mp} (-1)^{mu+mp} X2[L,s][mu,mp] X2[L,s][-mu,-mp]
// where X2[L,s] = CG-combine(X, X) components.
//
// R2 structure (product sharing): group components by channel pair
// {(mu,mp), (-mu,-mp)}; each distinct input product is computed ONCE (FMUL)
// and folded into every (L,s) accumulator it feeds with an FFMA-immediate.
//
// R3 fix (resubmitted; harness has not yet compiled it due to GPU timeouts):
// xidx is __host__ __device__ constexpr (harness compiles WITHOUT
// --expt-relaxed-constexpr), offset table inlined so no host constexpr
// array is ODR-used from device code.
// ============================================================================

namespace wk {

constexpr double cfact(int n) { double r = 1.0; for (int i = 2; i <= n; i++) r *= (double)i; return r; }

constexpr double csqrt(double v) {
    if (v <= 0.0) return 0.0;
    double g = v > 1.0 ? v : 1.0;
    for (int i = 0; i < 48; i++) g = 0.5 * (g + v / g);
    return g;
}

constexpr double cg_val(int l1, int l2, int L, int m1, int m2) {
    int dl = l1 > l2 ? l1 - l2 : l2 - l1;
    if (L < dl || L > l1 + l2) return 0.0;
    if (m1 < -l1 || m1 > l1 || m2 < -l2 || m2 > l2) return 0.0;
    int M = m1 + m2;
    if (M < -L || M > L) return 0.0;
    double pref0 = csqrt((2.0 * L + 1.0) * cfact(L + l1 - l2) * cfact(L - l1 + l2) *
                         cfact(l1 + l2 - L) / cfact(l1 + l2 + L + 1));
    double pref = pref0 * csqrt(cfact(L + M) * cfact(L - M) * cfact(l1 - m1) *
                                cfact(l1 + m1) * cfact(l2 - m2) * cfact(l2 + m2));
    double s = 0.0;
    for (int k = 0; k <= l1 + l2 - L; k++) {
        if (l1 - m1 - k < 0 || l2 + m2 - k < 0 || L - l2 + m1 + k < 0 || L - l1 - m2 + k < 0) continue;
        double d = cfact(k) * cfact(l1 + l2 - L - k) * cfact(l1 - m1 - k) *
                   cfact(l2 + m2 - k) * cfact(L - l2 + m1 + k) * cfact(L - l1 - m2 + k);
        s += (k & 1) ? (-1.0 / d) : (1.0 / d);
    }
    return pref * s;
}

struct CGTab { double v[4][4][4][7][7]; };
constexpr CGTab makeCG() {
    CGTab t{};
    for (int l1 = 0; l1 < 4; l1++)
        for (int l2 = 0; l2 < 4; l2++)
            for (int L = 0; L < 4; L++)
                for (int m1 = -l1; m1 <= l1; m1++)
                    for (int m2 = -l2; m2 <= l2; m2++)
                        t.v[l1][l2][L][m1 + 3][m2 + 3] = cg_val(l1, l2, L, m1, m2);
    return t;
}
constexpr CGTab CGT = makeCG();

// __host__ __device__: called from device-side constant expressions; the
// harness does NOT pass --expt-relaxed-constexpr. Offset table inlined
// (no host constexpr array may be ODR-used from device code).
__host__ __device__ constexpr int xidx(int l, int m, int mp) {
    int off = (l == 0) ? 0 : (l == 1) ? 1 : (l == 2) ? 10 : 35;
    return off + (m + l) * (2 * l + 1) + (mp + l);
}

constexpr int MAXP  = 4096;  // global distinct products
constexpr int MAXGG = 32;    // canonical (mu,mp) channel pairs (25)
constexpr int MAXC  = 7;     // (L,s) component slots per channel

struct Prog {
    int ng, np;
    int g_mu[MAXGG], g_mp[MAXGG], g_self[MAXGG], g_nc[MAXGG];
    int g_L[MAXGG][MAXC]; int g_S[MAXGG][MAXC];
    int g_p0[MAXGG + 1];
    int iaA[MAXP], ibA[MAXP], iaB[MAXP], ibB[MAXP];
    float cf[MAXP][MAXC];    // per-product coefficient per component slot
};

constexpr Prog build() {
    Prog P{};
    for (int mu = 0; mu <= 3; mu++)
        for (int mp = -3; mp <= 3; mp++) {
            if (mu == 0 && mp < 0) continue;               // canonical rep of +/- pair
            int amp = mp < 0 ? -mp : mp;
            int M = mu > amp ? mu : amp;
            int g = P.ng;
            P.g_mu[g] = mu; P.g_mp[g] = mp;
            P.g_self[g] = (mu == 0 && mp == 0) ? 1 : 0;
            // component slots (L,s) that exist for this channel
            int nc = 0;
            for (int L = M; L <= 3; L++)
                for (int si = 0; si < 2; si++) {
                    int s = si ? -1 : 1;
                    bool ex = false;
                    for (int l1 = 0; l1 < 4; l1++)
                        for (int l2 = l1; l2 < 4; l2++) {
                            if (L < l2 - l1 || L > l1 + l2) continue;
                            if (((((l1 + l2 + L) & 1) ? -1 : 1)) == s) ex = true;
                        }
                    if (!ex) continue;
                    P.g_L[g][nc] = L; P.g_S[g][nc] = s; nc++;
                }
            P.g_nc[g] = nc;
            P.g_p0[g] = P.np;
            // products with channel signature (m1+m2=mu, q1+q2=mp)
            for (int l1 = 0; l1 < 4; l1++)
                for (int l2 = l1; l2 < 4; l2++)
                    for (int m1 = -l1; m1 <= l1; m1++)
                        for (int q1 = -l1; q1 <= l1; q1++) {
                            int m2 = mu - m1, q2 = mp - q1;
                            if (m2 < -l2 || m2 > l2 || q2 < -l2 || q2 > l2) continue;
                            double f = 2.0;  // (l1,l2)<->(l2,l1) or in-block swap merge
                            if (l1 == l2) {
                                if (m1 > m2 || (m1 == m2 && q1 > q2)) continue;  // canonical
                                if (m1 == m2 && q1 == q2) f = 1.0;               // diagonal
                            }
                            float cfs[MAXC] = {};
                            bool any = false;
                            for (int j = 0; j < nc; j++) {
                                int L = P.g_L[g][j], s = P.g_S[g][j];
                                if (L < l2 - l1 || L > l1 + l2) continue;
                                if (((((l1 + l2 + L) & 1) ? -1 : 1)) != s) continue;
                                double c = f * CGT.v[l1][l2][L][m1 + 3][m2 + 3]
                                             * CGT.v[l1][l2][L][q1 + 3][q2 + 3];
                                if (c < 1e-12 && c > -1e-12) continue;
                                cfs[j] = (float)c; any = true;
                            }
                            if (!any) continue;
                            int p = P.np;
                            P.iaA[p] = xidx(l1,  m1,  q1); P.ibA[p] = xidx(l2,  m2,  q2);
                            P.iaB[p] = xidx(l1, -m1, -q1); P.ibB[p] = xidx(l2, -m2, -q2);
                            for (int j = 0; j < nc; j++) P.cf[p][j] = cfs[j];
                            P.np++;
                        }
            P.ng++;
        }
    P.g_p0[P.ng] = P.np;
    return P;
}

constexpr Prog PROG = build();
static_assert(PROG.ng <= MAXGG, "group overflow");
static_assert(PROG.np <= MAXP, "product overflow");
static_assert(PROG.g_mu[0] == 0 && PROG.g_mp[0] == 0, "group 0 must be (0,0)");
static_assert(PROG.g_L[0][0] == 0 && PROG.g_S[0][0] == 1, "slot (0,0,0) must be r2");
static_assert(PROG.g_self[0] == 1, "group 0 self-paired");

// fold one product into all component slots with nonzero coefficient
template <int NC, bool SELF, int P, int J>
__device__ __forceinline__ void accSlots(float pA, float pB,
                                         float (&cA)[NC], float (&cB)[NC]) {
    if constexpr (J < NC) {
        constexpr float c = PROG.cf[P][J];
        if constexpr (c != 0.0f) {
            cA[J] = fmaf(pA, c, cA[J]);               // FFMA-imm, rt=1
            if constexpr (!SELF) cB[J] = fmaf(pB, c, cB[J]);
        }
        accSlots<NC, SELF, P, J + 1>(pA, pB, cA, cB);
    }
}

// balanced binary recursion over the group's product range
template <int NC, bool SELF, int P0, int P1>
__device__ __forceinline__ void prodRange(const float (&x)[84],
                                          float (&cA)[NC], float (&cB)[NC]) {
    if constexpr (P1 - P0 == 1) {
        constexpr int iaA = PROG.iaA[P0], ibA = PROG.ibA[P0];
        float pA = x[iaA] * x[ibA];                   // FMUL (shared across slots)
        float pB = 0.0f;
        if constexpr (!SELF) {
            constexpr int iaB = PROG.iaB[P0], ibB = PROG.ibB[P0];
            pB = x[iaB] * x[ibB];
        }
        accSlots<NC, SELF, P0, 0>(pA, pB, cA, cB);
    } else if constexpr (P1 - P0 > 1) {
        constexpr int M = (P0 + P1) / 2;
        prodRange<NC, SELF, P0, M>(x, cA, cB);
        prodRange<NC, SELF, M, P1>(x, cA, cB);
    }
}

template <int G, int NC, bool SELF, int J>
__device__ __forceinline__ void epilogue(const float (&x)[84],
                                         float (&cA)[NC], float (&cB)[NC],
                                         float& r2, float& r3, float& r4) {
    if constexpr (J < NC) {
        constexpr int L  = PROG.g_L[G][J];
        constexpr int S  = PROG.g_S[G][J];
        constexpr int mu = PROG.g_mu[G];
        constexpr int mp = PROG.g_mp[G];
        constexpr float sg  = (((mu + mp) & 1) != 0) ? -1.0f : 1.0f;
        constexpr float inv = 1.0f / (float)(2 * L + 1);

        float a = cA[J];
        float b = SELF ? cA[J] : cB[J];

        if constexpr (G == 0 && J == 0) r2 = a;       // X2[0,+][0,0]

        constexpr float w4 = (SELF ? 1.0f : 2.0f) * sg * inv;
        r4 = fmaf(w4 * a, b, r4);

        if constexpr (S == 1) {
            constexpr float w3 = sg * inv;
            constexpr int iA = xidx(L, -mu, -mp);
            r3 = fmaf(w3 * a, x[iA], r3);
            if constexpr (!SELF) {
                constexpr int iB = xidx(L, mu, mp);
                r3 = fmaf(w3 * b, x[iB], r3);
            }
        }
        epilogue<G, NC, SELF, J + 1>(x, cA, cB, r2, r3, r4);
    }
}

template <int G>
__device__ __forceinline__ void doGroups(const float (&x)[84],
                                         float& r2, float& r3, float& r4) {
    if constexpr (G < PROG.ng) {
        constexpr int  NC   = PROG.g_nc[G];
        constexpr bool SELF = (PROG.g_self[G] != 0);
        constexpr int  P0   = PROG.g_p0[G];
        constexpr int  P1   = PROG.g_p0[G + 1];

        float cA[NC] = {};
        float cB[NC] = {};
        prodRange<NC, SELF, P0, P1>(x, cA, cB);
        epilogue<G, NC, SELF, 0>(x, cA, cB, r2, r3, r4);
        doGroups<G + 1>(x, r2, r3, r4);
    }
}

} // namespace wk

constexpr int TPB = 128;

// Cooperative coalesced load of a [TPB x W] block-contiguous slab into smem.
template <int W>
__device__ __forceinline__ void stage_slab(float* __restrict__ s,
                                           const float* __restrict__ g,
                                           long long base_elem,
                                           long long total_elems,
                                           int tid) {
    constexpr int SLAB = TPB * W;
    if ((base_elem & 3LL) == 0) {
        const float4* g4 = reinterpret_cast<const float4*>(g + base_elem);
        float4* s4 = reinterpret_cast<float4*>(s);
        constexpr int N4 = SLAB / 4;
        long long avail4 = (total_elems - base_elem) >> 2;
#pragma unroll
        for (int i = tid; i < N4; i += TPB) {
            if ((long long)i < avail4) s4[i] = g4[i];
        }
        long long done = avail4 << 2;
        for (long long e = done + tid; e < SLAB && base_elem + e < total_elems; e += TPB)
            s[e] = g[base_elem + e];
    } else {
#pragma unroll
        for (int i = tid; i < SLAB; i += TPB) {
            if (base_elem + i < total_elems) s[i] = g[base_elem + i];
        }
    }
}

__global__ void __launch_bounds__(TPB)
wigner_reduced_kernel(const float* __restrict__ p0, const float* __restrict__ p1,
                      const float* __restrict__ p2, const float* __restrict__ p3,
                      float* __restrict__ out, int B) {
    __shared__ float s1[TPB * 9];
    __shared__ float s2[TPB * 25];
    __shared__ float s3[TPB * 49];

    const int tid = threadIdx.x;
    const long long blockBase = (long long)blockIdx.x * TPB;

    stage_slab<9>(s1, p1, blockBase * 9, (long long)B * 9, tid);
    stage_slab<25>(s2, p2, blockBase * 25, (long long)B * 25, tid);
    stage_slab<49>(s3, p3, blockBase * 49, (long long)B * 49, tid);
    __syncthreads();

    const long long b = blockBase + tid;
    if (b >= B) return;

    float x[84];
    x[0] = p0[b];
#pragma unroll
    for (int i = 0; i < 9; i++)  x[1 + i]  = s1[tid * 9 + i];
#pragma unroll
    for (int i = 0; i < 25; i++) x[10 + i] = s2[tid * 25 + i];
#pragma unroll
    for (int i = 0; i < 49; i++) x[35 + i] = s3[tid * 49 + i];

    float r2 = 0.0f, r3 = 0.0f, r4 = 0.0f;
    wk::doGroups<0>(x, r2, r3, r4);

    reinterpret_cast<float4*>(out)[b] = make_float4(x[0], r2, r3, r4);
}

extern "C" void kernel_launch(void* const* d_in, const int* in_sizes, int n_in,
                              void* d_out, int out_size) {
    const float* p0 = (const float*)d_in[0];
    const float* p1 = (const float*)d_in[1];
    const float* p2 = (const float*)d_in[2];
    const float* p3 = (const float*)d_in[3];
    float* out = (float*)d_out;
    int B = in_sizes[0];
    int blocks = (B + TPB - 1) / TPB;
    wigner_reduced_kernel<<<blocks, TPB>>>(p0, p1, p2, p3, out, B);
}

// round 10
// speedup vs baseline: 1.0135x; 1.0135x over previous
#include <cuda_runtime.h>
#include <cstdint>

// ============================================================================
// WignerKernelReducedCost — GB300 sm_103a
//
// Math reduction (see R0): per batch element b:
//   r1 = x0[0,0];  r2 = X2[0,+1][0,0]
//   r3 = sum_{L,s=+1} 1/(2L+1) sum_{mu,mp} (-1)^{mu+mp} X2[L,+][mu,mp] x_L[-mu,-mp]
//   r4 = sum_{L,s}    1/(2L+1) sum_{mu,mp} (-1)^{mu+mp} X2[L,s][mu,mp] X2[L,s][-mu,-mp]
//
// R2 structure: channel-pair grouping + product sharing (1 FMUL per distinct
// product, FFMA-imm per (product, L-slot) coefficient).
//
// R7 measured: 67.2us pass; issue=53%, fma=43%, occ=23.3% -> latency-bound on
// accumulator chains (per-warp IPC ~0.14, no spills, mem idle).
// Change under test (resubmitted through repeated infra timeouts): DUAL
// ACCUMULATORS per slot (even/odd product parity) to double dependency
// distance on every chain; __launch_bounds__(128,4) pins 128 regs / 4 CTAs
// so the extra transient registers cannot drop occupancy.
// ============================================================================

namespace wk {

constexpr double cfact(int n) { double r = 1.0; for (int i = 2; i <= n; i++) r *= (double)i; return r; }

constexpr double csqrt(double v) {
    if (v <= 0.0) return 0.0;
    double g = v > 1.0 ? v : 1.0;
    for (int i = 0; i < 48; i++) g = 0.5 * (g + v / g);
    return g;
}

constexpr double cg_val(int l1, int l2, int L, int m1, int m2) {
    int dl = l1 > l2 ? l1 - l2 : l2 - l1;
    if (L < dl || L > l1 + l2) return 0.0;
    if (m1 < -l1 || m1 > l1 || m2 < -l2 || m2 > l2) return 0.0;
    int M = m1 + m2;
    if (M < -L || M > L) return 0.0;
    double pref0 = csqrt((2.0 * L + 1.0) * cfact(L + l1 - l2) * cfact(L - l1 + l2) *
                         cfact(l1 + l2 - L) / cfact(l1 + l2 + L + 1));
    double pref = pref0 * csqrt(cfact(L + M) * cfact(L - M) * cfact(l1 - m1) *
                                cfact(l1 + m1) * cfact(l2 - m2) * cfact(l2 + m2));
    double s = 0.0;
    for (int k = 0; k <= l1 + l2 - L; k++) {
        if (l1 - m1 - k < 0 || l2 + m2 - k < 0 || L - l2 + m1 + k < 0 || L - l1 - m2 + k < 0) continue;
        double d = cfact(k) * cfact(l1 + l2 - L - k) * cfact(l1 - m1 - k) *
                   cfact(l2 + m2 - k) * cfact(L - l2 + m1 + k) * cfact(L - l1 - m2 + k);
        s += (k & 1) ? (-1.0 / d) : (1.0 / d);
    }
    return pref * s;
}

struct CGTab { double v[4][4][4][7][7]; };
constexpr CGTab makeCG() {
    CGTab t{};
    for (int l1 = 0; l1 < 4; l1++)
        for (int l2 = 0; l2 < 4; l2++)
            for (int L = 0; L < 4; L++)
                for (int m1 = -l1; m1 <= l1; m1++)
                    for (int m2 = -l2; m2 <= l2; m2++)
                        t.v[l1][l2][L][m1 + 3][m2 + 3] = cg_val(l1, l2, L, m1, m2);
    return t;
}
constexpr CGTab CGT = makeCG();

// __host__ __device__: referenced from device-side constant expressions; the
// harness compiles WITHOUT --expt-relaxed-constexpr. Offset table inlined.
__host__ __device__ constexpr int xidx(int l, int m, int mp) {
    int off = (l == 0) ? 0 : (l == 1) ? 1 : (l == 2) ? 10 : 35;
    return off + (m + l) * (2 * l + 1) + (mp + l);
}

constexpr int MAXP  = 4096;  // global distinct products
constexpr int MAXGG = 32;    // canonical (mu,mp) channel pairs (25)
constexpr int MAXC  = 7;     // (L,s) component slots per channel

struct Prog {
    int ng, np;
    int g_mu[MAXGG], g_mp[MAXGG], g_self[MAXGG], g_nc[MAXGG];
    int g_L[MAXGG][MAXC]; int g_S[MAXGG][MAXC];
    int g_p0[MAXGG + 1];
    int iaA[MAXP], ibA[MAXP], iaB[MAXP], ibB[MAXP];
    float cf[MAXP][MAXC];    // per-product coefficient per component slot
};

constexpr Prog build() {
    Prog P{};
    for (int mu = 0; mu <= 3; mu++)
        for (int mp = -3; mp <= 3; mp++) {
            if (mu == 0 && mp < 0) continue;               // canonical rep of +/- pair
            int amp = mp < 0 ? -mp : mp;
            int M = mu > amp ? mu : amp;
            int g = P.ng;
            P.g_mu[g] = mu; P.g_mp[g] = mp;
            P.g_self[g] = (mu == 0 && mp == 0) ? 1 : 0;
            // component slots (L,s) that exist for this channel
            int nc = 0;
            for (int L = M; L <= 3; L++)
                for (int si = 0; si < 2; si++) {
                    int s = si ? -1 : 1;
                    bool ex = false;
                    for (int l1 = 0; l1 < 4; l1++)
                        for (int l2 = l1; l2 < 4; l2++) {
                            if (L < l2 - l1 || L > l1 + l2) continue;
                            if (((((l1 + l2 + L) & 1) ? -1 : 1)) == s) ex = true;
                        }
                    if (!ex) continue;
                    P.g_L[g][nc] = L; P.g_S[g][nc] = s; nc++;
                }
            P.g_nc[g] = nc;
            P.g_p0[g] = P.np;
            // products with channel signature (m1+m2=mu, q1+q2=mp)
            for (int l1 = 0; l1 < 4; l1++)
                for (int l2 = l1; l2 < 4; l2++)
                    for (int m1 = -l1; m1 <= l1; m1++)
                        for (int q1 = -l1; q1 <= l1; q1++) {
                            int m2 = mu - m1, q2 = mp - q1;
                            if (m2 < -l2 || m2 > l2 || q2 < -l2 || q2 > l2) continue;
                            double f = 2.0;  // (l1,l2)<->(l2,l1) or in-block swap merge
                            if (l1 == l2) {
                                if (m1 > m2 || (m1 == m2 && q1 > q2)) continue;  // canonical
                                if (m1 == m2 && q1 == q2) f = 1.0;               // diagonal
                            }
                            float cfs[MAXC] = {};
                            bool any = false;
                            for (int j = 0; j < nc; j++) {
                                int L = P.g_L[g][j], s = P.g_S[g][j];
                                if (L < l2 - l1 || L > l1 + l2) continue;
                                if (((((l1 + l2 + L) & 1) ? -1 : 1)) != s) continue;
                                double c = f * CGT.v[l1][l2][L][m1 + 3][m2 + 3]
                                             * CGT.v[l1][l2][L][q1 + 3][q2 + 3];
                                if (c < 1e-12 && c > -1e-12) continue;
                                cfs[j] = (float)c; any = true;
                            }
                            if (!any) continue;
                            int p = P.np;
                            P.iaA[p] = xidx(l1,  m1,  q1); P.ibA[p] = xidx(l2,  m2,  q2);
                            P.iaB[p] = xidx(l1, -m1, -q1); P.ibB[p] = xidx(l2, -m2, -q2);
                            for (int j = 0; j < nc; j++) P.cf[p][j] = cfs[j];
                            P.np++;
                        }
            P.ng++;
        }
    P.g_p0[P.ng] = P.np;
    return P;
}

constexpr Prog PROG = build();
static_assert(PROG.ng <= MAXGG, "group overflow");
static_assert(PROG.np <= MAXP, "product overflow");
static_assert(PROG.g_mu[0] == 0 && PROG.g_mp[0] == 0, "group 0 must be (0,0)");
static_assert(PROG.g_L[0][0] == 0 && PROG.g_S[0][0] == 1, "slot (0,0,0) must be r2");
static_assert(PROG.g_self[0] == 1, "group 0 self-paired");

// fold one product into all component slots with nonzero coefficient.
// PAR selects the even/odd accumulator bank (dependency-chain splitting).
template <int NC, bool SELF, int P, int J, bool PAR>
__device__ __forceinline__ void accSlots(float pA, float pB,
                                         float (&cA0)[NC], float (&cB0)[NC],
                                         float (&cA1)[NC], float (&cB1)[NC]) {
    if constexpr (J < NC) {
        constexpr float c = PROG.cf[P][J];
        if constexpr (c != 0.0f) {
            if constexpr (!PAR) {
                cA0[J] = fmaf(pA, c, cA0[J]);          // FFMA-imm, rt=1
                if constexpr (!SELF) cB0[J] = fmaf(pB, c, cB0[J]);
            } else {
                cA1[J] = fmaf(pA, c, cA1[J]);
                if constexpr (!SELF) cB1[J] = fmaf(pB, c, cB1[J]);
            }
        }
        accSlots<NC, SELF, P, J + 1, PAR>(pA, pB, cA0, cB0, cA1, cB1);
    }
}

// balanced binary recursion over the group's product range
template <int NC, bool SELF, int P0, int P1>
__device__ __forceinline__ void prodRange(const float (&x)[84],
                                          float (&cA0)[NC], float (&cB0)[NC],
                                          float (&cA1)[NC], float (&cB1)[NC]) {
    if constexpr (P1 - P0 == 1) {
        constexpr int iaA = PROG.iaA[P0], ibA = PROG.ibA[P0];
        float pA = x[iaA] * x[ibA];                   // FMUL (shared across slots)
        float pB = 0.0f;
        if constexpr (!SELF) {
            constexpr int iaB = PROG.iaB[P0], ibB = PROG.ibB[P0];
            pB = x[iaB] * x[ibB];
        }
        constexpr bool PAR = ((P0 & 1) != 0);          // even/odd bank by product index
        accSlots<NC, SELF, P0, 0, PAR>(pA, pB, cA0, cB0, cA1, cB1);
    } else if constexpr (P1 - P0 > 1) {
        constexpr int M = (P0 + P1) / 2;
        prodRange<NC, SELF, P0, M>(x, cA0, cB0, cA1, cB1);
        prodRange<NC, SELF, M, P1>(x, cA0, cB0, cA1, cB1);
    }
}

template <int G, int NC, bool SELF, int J>
__device__ __forceinline__ void epilogue(const float (&x)[84],
                                         float (&cA0)[NC], float (&cB0)[NC],
                                         float (&cA1)[NC], float (&cB1)[NC],
                                         float& r2, float& r3, float& r4) {
    if constexpr (J < NC) {
        constexpr int L  = PROG.g_L[G][J];
        constexpr int S  = PROG.g_S[G][J];
        constexpr int mu = PROG.g_mu[G];
        constexpr int mp = PROG.g_mp[G];
        constexpr float sg  = (((mu + mp) & 1) != 0) ? -1.0f : 1.0f;
        constexpr float inv = 1.0f / (float)(2 * L + 1);

        float a = cA0[J] + cA1[J];
        float b = SELF ? a : (cB0[J] + cB1[J]);

        if constexpr (G == 0 && J == 0) r2 = a;       // X2[0,+][0,0]

        constexpr float w4 = (SELF ? 1.0f : 2.0f) * sg * inv;
        r4 = fmaf(w4 * a, b, r4);

        if constexpr (S == 1) {
            constexpr float w3 = sg * inv;
            constexpr int iA = xidx(L, -mu, -mp);
            r3 = fmaf(w3 * a, x[iA], r3);
            if constexpr (!SELF) {
                constexpr int iB = xidx(L, mu, mp);
                r3 = fmaf(w3 * b, x[iB], r3);
            }
        }
        epilogue<G, NC, SELF, J + 1>(x, cA0, cB0, cA1, cB1, r2, r3, r4);
    }
}

template <int G>
__device__ __forceinline__ void doGroups(const float (&x)[84],
                                         float& r2, float& r3, float& r4) {
    if constexpr (G < PROG.ng) {
        constexpr int  NC   = PROG.g_nc[G];
        constexpr bool SELF = (PROG.g_self[G] != 0);
        constexpr int  P0   = PROG.g_p0[G];
        constexpr int  P1   = PROG.g_p0[G + 1];

        float cA0[NC] = {};
        float cB0[NC] = {};
        float cA1[NC] = {};
        float cB1[NC] = {};
        prodRange<NC, SELF, P0, P1>(x, cA0, cB0, cA1, cB1);
        epilogue<G, NC, SELF, 0>(x, cA0, cB0, cA1, cB1, r2, r3, r4);
        doGroups<G + 1>(x, r2, r3, r4);
    }
}

} // namespace wk

constexpr int TPB = 128;

// Cooperative coalesced load of a [TPB x W] block-contiguous slab into smem.
template <int W>
__device__ __forceinline__ void stage_slab(float* __restrict__ s,
                                           const float* __restrict__ g,
                                           long long base_elem,
                                           long long total_elems,
                                           int tid) {
    constexpr int SLAB = TPB * W;
    if ((base_elem & 3LL) == 0) {
        const float4* g4 = reinterpret_cast<const float4*>(g + base_elem);
        float4* s4 = reinterpret_cast<float4*>(s);
        constexpr int N4 = SLAB / 4;
        long long avail4 = (total_elems - base_elem) >> 2;
#pragma unroll
        for (int i = tid; i < N4; i += TPB) {
            if ((long long)i < avail4) s4[i] = g4[i];
        }
        long long done = avail4 << 2;
        for (long long e = done + tid; e < SLAB && base_elem + e < total_elems; e += TPB)
            s[e] = g[base_elem + e];
    } else {
#pragma unroll
        for (int i = tid; i < SLAB; i += TPB) {
            if (base_elem + i < total_elems) s[i] = g[base_elem + i];
        }
    }
}

__global__ void __launch_bounds__(TPB, 4)
wigner_reduced_kernel(const float* __restrict__ p0, const float* __restrict__ p1,
                      const float* __restrict__ p2, const float* __restrict__ p3,
                      float* __restrict__ out, int B) {
    __shared__ float s1[TPB * 9];
    __shared__ float s2[TPB * 25];
    __shared__ float s3[TPB * 49];

    const int tid = threadIdx.x;
    const long long blockBase = (long long)blockIdx.x * TPB;

    stage_slab<9>(s1, p1, blockBase * 9, (long long)B * 9, tid);
    stage_slab<25>(s2, p2, blockBase * 25, (long long)B * 25, tid);
    stage_slab<49>(s3, p3, blockBase * 49, (long long)B * 49, tid);
    __syncthreads();

    const long long b = blockBase + tid;
    if (b >= B) return;

    float x[84];
    x[0] = p0[b];
#pragma unroll
    for (int i = 0; i < 9; i++)  x[1 + i]  = s1[tid * 9 + i];
#pragma unroll
    for (int i = 0; i < 25; i++) x[10 + i] = s2[tid * 25 + i];
#pragma unroll
    for (int i = 0; i < 49; i++) x[35 + i] = s3[tid * 49 + i];

    float r2 = 0.0f, r3 = 0.0f, r4 = 0.0f;
    wk::doGroups<0>(x, r2, r3, r4);

    reinterpret_cast<float4*>(out)[b] = make_float4(x[0], r2, r3, r4);
}

extern "C" void kernel_launch(void* const* d_in, const int* in_sizes, int n_in,
                              void* d_out, int out_size) {
    const float* p0 = (const float*)d_in[0];
    const float* p1 = (const float*)d_in[1];
    const float* p2 = (const float*)d_in[2];
    const float* p3 = (const float*)d_in[3];
    float* out = (float*)d_out;
    int B = in_sizes[0];
    int blocks = (B + TPB - 1) / TPB;
    wigner_reduced_kernel<<<blocks, TPB>>>(p0, p1, p2, p3, out, B);
}